// round 1
// baseline (speedup 1.0000x reference)
#include <cuda_runtime.h>
#include <stdint.h>

// Problem constants
#define NT   4000
#define NS   16
#define NR   512
#define NCOL (NS * NR)        // 8192 columns
#define NSEG 20
#define SEG_LEN (NT / NSEG)   // 200
#define TPB  256
#define COL_BLOCKS (NCOL / TPB)  // 32

// Scratch: per-(segment, column) packed argmax for x and y.
// packed = (float_bits(v*v) << 32) | ~t   -> max() gives argmax with
// first-index tiebreak (v*v >= 0 so IEEE bits order as unsigned).
__device__ unsigned long long g_px[NSEG * NCOL];
__device__ unsigned long long g_py[NSEG * NCOL];
__device__ unsigned long long g_accum;

__global__ void zero_accum_kernel() {
    g_accum = 0ull;
}

// Kernel 1: each thread scans one 200-sample segment of one column for both
// x and y. Warp-adjacent threads read adjacent r -> fully coalesced 128B lines.
__global__ __launch_bounds__(TPB) void seg_argmax_kernel(
    const float* __restrict__ x, const float* __restrict__ y)
{
    const int col = blockIdx.x * TPB + threadIdx.x;   // 0..8191
    const int seg = blockIdx.y;                       // 0..NSEG-1
    const int t0  = seg * SEG_LEN;

    const float* __restrict__ px = x + (size_t)t0 * NCOL + col;
    const float* __restrict__ py = y + (size_t)t0 * NCOL + col;

    unsigned long long bx = 0ull, by = 0ull;

    #pragma unroll 8
    for (int i = 0; i < SEG_LEN; ++i) {
        float vx = px[(size_t)i * NCOL];
        float vy = py[(size_t)i * NCOL];
        float sx = vx * vx;
        float sy = vy * vy;
        unsigned int ti = ~(unsigned int)(t0 + i);
        unsigned long long kx =
            ((unsigned long long)__float_as_uint(sx) << 32) | ti;
        unsigned long long ky =
            ((unsigned long long)__float_as_uint(sy) << 32) | ti;
        bx = (kx > bx) ? kx : bx;
        by = (ky > by) ? ky : by;
    }

    g_px[seg * NCOL + col] = bx;
    g_py[seg * NCOL + col] = by;
}

// Kernel 2: reduce over segments per column, form (tx-ty)^2 (exact int64),
// block-reduce, one atomicAdd per block (exact integer -> deterministic).
__global__ __launch_bounds__(TPB) void reduce_mse_kernel()
{
    const int col = blockIdx.x * TPB + threadIdx.x;

    unsigned long long bx = 0ull, by = 0ull;
    #pragma unroll
    for (int s = 0; s < NSEG; ++s) {
        unsigned long long kx = g_px[s * NCOL + col];
        unsigned long long ky = g_py[s * NCOL + col];
        bx = (kx > bx) ? kx : bx;
        by = (ky > by) ? ky : by;
    }

    int tx = (int)(~(unsigned int)(bx & 0xffffffffull));
    int ty = (int)(~(unsigned int)(by & 0xffffffffull));
    long long d = (long long)tx - (long long)ty;
    unsigned long long sq = (unsigned long long)(d * d);

    // warp reduce
    #pragma unroll
    for (int off = 16; off > 0; off >>= 1)
        sq += __shfl_down_sync(0xffffffffu, sq, off);

    __shared__ unsigned long long warp_sums[TPB / 32];
    const int lane = threadIdx.x & 31;
    const int wid  = threadIdx.x >> 5;
    if (lane == 0) warp_sums[wid] = sq;
    __syncthreads();

    if (wid == 0) {
        unsigned long long v = (lane < TPB / 32) ? warp_sums[lane] : 0ull;
        #pragma unroll
        for (int off = 4; off > 0; off >>= 1)
            v += __shfl_down_sync(0xffffffffu, v, off);
        if (lane == 0)
            atomicAdd(&g_accum, v);
    }
}

__global__ void finalize_kernel(float* __restrict__ out)
{
    out[0] = (float)((double)g_accum / (double)NCOL);
}

extern "C" void kernel_launch(void* const* d_in, const int* in_sizes, int n_in,
                              void* d_out, int out_size)
{
    const float* x = (const float*)d_in[0];
    const float* y = (const float*)d_in[1];
    float* out = (float*)d_out;

    zero_accum_kernel<<<1, 1>>>();

    dim3 grid1(COL_BLOCKS, NSEG);
    seg_argmax_kernel<<<grid1, TPB>>>(x, y);

    reduce_mse_kernel<<<COL_BLOCKS, TPB>>>();

    finalize_kernel<<<1, 1>>>(out);
}